// round 7
// baseline (speedup 1.0000x reference)
#include <cuda_runtime.h>

// KMeansProbSampler: 8 iterations of weighted k-means scatter on a 1024x1024
// heatmap with 128 clusters.
//
// R7: 2D-tile pruning.
//   key_k(r,c) = fmaf(c, -2cc_k, fmaf(r, -2cr_k, n_k)),  n_k = cr_k^2+cc_k^2
//   (shifted squared distance; the (r^2+c^2) shift is per-pixel and thus
//   argmin-invariant). key is linear in r and c, and fma is correctly rounded
//   (weakly monotone per variable), so min/max over a rectangle are attained
//   at its 4 corners using the *identical* fmaf composition as the scan.
// Block = 32x32 pixel tile (grid 32x32). Warp = 8x16 sub-tile,
// thread = 4 consecutive pixels of one row.
// Per warp:  evaluate 4-corner keys per cluster (4 clusters/lane),
//   UB = min_k max_corner(key_k)  ->  keep k iff min_corner(key_k) <= UB
//   (per-pixel winner always kept: key_w(p) <= key_k(p) <= max_corner(key_k)).
//   Ballot-compact survivors ascending into shared as float4(n,-2cr,-2cc,idx).
// Scan: per pixel over survivors, strict '<' ascending -> lowest index on
//   ties, matching argmin. Exact d2 recomputed for the winner only;
//   w = h * min(1, rsqrt(d2)). Run-combined shared atomics, then global.

#define HH 1024
#define WW 1024
#define CC 128
#define NITER 8
#define PX 4
#define TPB 256
#define NWARP (TPB / 32)
#define BT 32                 // block tile edge (32x32 pixels)

__device__ float g_bufA[CC * 2];
__device__ float g_bufB[CC * 2];

__global__ void zero_kernel(float* t) {
    t[threadIdx.x] = 0.0f;
}

__global__ __launch_bounds__(TPB) void kmeans_iter_kernel(
    const float* __restrict__ clusters,   // [C,2] (row, col)
    const float* __restrict__ heat,       // [H,W]
    float* __restrict__ target)           // [C,2] output sums (pre-zeroed)
{
    __shared__ __align__(16) float4 sh_surv[NWARP][CC];  // (n,-2cr,-2cc,idx)
    __shared__ float2 sh_pos[CC];                        // (cr, cc)
    __shared__ float  sacc[CC * 2];

    const int t    = threadIdx.x;
    const int w    = t >> 5;
    const int lane = t & 31;

    // block tile origin
    const int r0 = blockIdx.y * BT;
    const int c0 = blockIdx.x * BT;
    // warp sub-tile: 8 rows x 16 cols;  warps laid out 4 (rows) x 2 (cols)
    const int wr0 = r0 + (w >> 1) * 8;
    const int wc0 = c0 + (w & 1) * 16;
    // thread pixels: one row, 4 consecutive cols
    const int   prow = wr0 + (lane >> 2);
    const int   pcol = wc0 + (lane & 3) * PX;
    const float rf   = (float)prow;

    if (t < CC) {
        sh_pos[t] = make_float2(clusters[2 * t], clusters[2 * t + 1]);
    }
    sacc[t] = 0.0f;
    __syncthreads();

    // ---- per-warp 2D pruning: 4 clusters per lane ----
    const float rLo = (float)wr0, rHi = (float)(wr0 + 7);
    const float cLo = (float)wc0, cHi = (float)(wc0 + 15);

    float3 cl[4];
    float  mn[4];
    float  ubl = 3.4e38f;
#pragma unroll
    for (int q = 0; q < 4; q++) {
        int    k  = lane + 32 * q;
        float2 p  = sh_pos[k];
        float  n  = fmaf(p.x, p.x, p.y * p.y);
        float  m2r = -2.0f * p.x;
        float  m2c = -2.0f * p.y;
        cl[q] = make_float3(n, m2r, m2c);
        // corner keys with the exact fmaf composition used by the scan
        float bLo = fmaf(rLo, m2r, n);
        float bHi = fmaf(rHi, m2r, n);
        float k00 = fmaf(cLo, m2c, bLo);
        float k01 = fmaf(cHi, m2c, bLo);
        float k10 = fmaf(cLo, m2c, bHi);
        float k11 = fmaf(cHi, m2c, bHi);
        mn[q]     = fminf(fminf(k00, k01), fminf(k10, k11));
        float mx  = fmaxf(fmaxf(k00, k01), fmaxf(k10, k11));
        ubl = fminf(ubl, mx);
    }
    float ub = ubl;
#pragma unroll
    for (int off = 16; off; off >>= 1)
        ub = fminf(ub, __shfl_xor_sync(0xffffffffu, ub, off));

    int base = 0;
#pragma unroll
    for (int q = 0; q < 4; q++) {                 // ascending q, ascending lane
        bool     p   = (mn[q] <= ub);             // non-strict: ties survive
        unsigned bal = __ballot_sync(0xffffffffu, p);
        int      pos = base + __popc(bal & ((1u << lane) - 1u));
        if (p) {
            sh_surv[w][pos] = make_float4(cl[q].x, cl[q].y, cl[q].z,
                                          __int_as_float(lane + 32 * q));
        }
        base += __popc(bal);
    }
    const int nsurv = base;
    __syncwarp();

    // ---- per-pixel scan over survivors ----
    const float cf0 = (float)pcol;
    const float cfs[PX] = {cf0, cf0 + 1.0f, cf0 + 2.0f, cf0 + 3.0f};
    float4 hv = *reinterpret_cast<const float4*>(heat + prow * WW + pcol);
    const float heats[PX] = {hv.x, hv.y, hv.z, hv.w};

    float bm0 = 3.4e38f, bm1 = 3.4e38f, bm2 = 3.4e38f, bm3 = 3.4e38f;
    float bf0 = 0.0f, bf1 = 0.0f, bf2 = 0.0f, bf3 = 0.0f;
    for (int i = 0; i < nsurv; i++) {
        float4 s  = sh_surv[w][i];
        float  b2 = fmaf(rf, s.y, s.x);
        float  k0 = fmaf(cfs[0], s.z, b2);
        float  k1 = fmaf(cfs[1], s.z, b2);
        float  k2 = fmaf(cfs[2], s.z, b2);
        float  k3 = fmaf(cfs[3], s.z, b2);
        if (k0 < bm0) { bm0 = k0; bf0 = s.w; }   // strict '<': lowest idx wins
        if (k1 < bm1) { bm1 = k1; bf1 = s.w; }
        if (k2 < bm2) { bm2 = k2; bf2 = s.w; }
        if (k3 < bm3) { bm3 = k3; bf3 = s.w; }
    }
    const int bests[PX] = { __float_as_int(bf0), __float_as_int(bf1),
                            __float_as_int(bf2), __float_as_int(bf3) };

    // ---- epilogue: exact d2 for winners, run-combined shared atomics ----
    int   curBest = -1;
    float ws = 0.0f, wc = 0.0f;
#pragma unroll
    for (int j = 0; j < PX; j++) {
        int    best = bests[j];
        float2 p    = sh_pos[best];
        float  dr   = rf - p.x;
        float  dc   = cfs[j] - p.y;
        float  d2   = fmaf(dr, dr, dc * dc);
        float  wgt  = heats[j] * fminf(1.0f, rsqrtf(d2));

        if (best == curBest) {
            ws += wgt;
            wc  = fmaf(wgt, cfs[j], wc);
        } else {
            if (curBest >= 0) {
                atomicAdd(&sacc[2 * curBest],     ws * rf);
                atomicAdd(&sacc[2 * curBest + 1], wc);
            }
            curBest = best;
            ws = wgt;
            wc = wgt * cfs[j];
        }
    }
    atomicAdd(&sacc[2 * curBest],     ws * rf);
    atomicAdd(&sacc[2 * curBest + 1], wc);

    __syncthreads();
    atomicAdd(&target[t], sacc[t]);
}

extern "C" void kernel_launch(void* const* d_in, const int* in_sizes, int n_in,
                              void* d_out, int out_size)
{
    const float* clusters = (const float*)d_in[0];
    const float* heat     = (const float*)d_in[1];
    if (in_sizes[0] != CC * 2) {  // robustness to metadata order
        const float* tmp = clusters; clusters = heat; heat = tmp;
    }

    float* bufA = nullptr;
    float* bufB = nullptr;
    cudaGetSymbolAddress((void**)&bufA, g_bufA);
    cudaGetSymbolAddress((void**)&bufB, g_bufB);
    float* out = (float*)d_out;

    dim3 grid(WW / BT, HH / BT);
    const float* cur = clusters;
    for (int it = 0; it < NITER; it++) {
        float* target;
        if (it == NITER - 1)      target = out;
        else if ((it & 1) == 0)   target = bufA;
        else                      target = bufB;

        zero_kernel<<<1, CC * 2>>>(target);
        kmeans_iter_kernel<<<grid, TPB>>>(cur, heat, target);
        cur = target;
    }
}